// round 1
// baseline (speedup 1.0000x reference)
#include <cuda_runtime.h>

#define Nn 50000
#define Ee 600000
#define Hh 128
#define Gg 64

// ---- scratch (static __device__ — no allocations) ----
__device__ float g_h[Nn * Hh];      // GEMM output (per layer)
__device__ float g_acc0[Nn * Hh];   // aggregation ping
__device__ float g_acc1[Nn * Hh];   // aggregation pong
__device__ float g_dinv[Nn];
__device__ int   g_deg[Nn];
__device__ float g_pooled[Gg * Hh];
__device__ int   g_cnt[Gg];

// ------------------------------------------------------------------
// init: deg=1 (self loop), pooled=0, cnt=0
// ------------------------------------------------------------------
__global__ void init_kernel() {
    int i = blockIdx.x * blockDim.x + threadIdx.x;
    if (i < Nn) g_deg[i] = 1;
    if (i < Gg * Hh) g_pooled[i] = 0.f;
    if (i < Gg) g_cnt[i] = 0;
}

__global__ void deg_kernel(const int* __restrict__ dst) {
    int e = blockIdx.x * blockDim.x + threadIdx.x;
    if (e < Ee) atomicAdd(&g_deg[dst[e]], 1);
}

__global__ void dinv_kernel() {
    int i = blockIdx.x * blockDim.x + threadIdx.x;
    if (i < Nn) g_dinv[i] = rsqrtf((float)g_deg[i]);
}

// ------------------------------------------------------------------
// GEMM: h = f(in) @ W, where f(v) = apply_f ? relu(v + bprev) : v
// Epilogue: hout = h;  accout = h * dinv^2   (self-loop init of aggregator)
// Tile: 64 rows x 128 cols per block, 256 threads, each thread 8x4 microtile.
// smem: in_s 64*128 + W_s 128*128 floats = 96 KB dynamic.
// ------------------------------------------------------------------
__global__ void gemm_kernel(const float* __restrict__ in, const float* __restrict__ W,
                            const float* __restrict__ bprev, int apply_f,
                            float* __restrict__ hout, float* __restrict__ accout) {
    extern __shared__ float sm[];
    float* in_s = sm;              // [64][128]
    float* W_s  = sm + 64 * Hh;    // [128][128]
    int tid = threadIdx.x;
    int r0 = blockIdx.x * 64;

    // load W (128x128) — 4096 float4 / 256 threads = 16 each
#pragma unroll
    for (int i = 0; i < 16; i++) {
        int fid = tid + i * 256;
        ((float4*)W_s)[fid] = ((const float4*)W)[fid];
    }
    // load input tile (64x128) with fused bias+relu transform
#pragma unroll
    for (int i = 0; i < 8; i++) {
        int fid = tid + i * 256;      // 0..2047
        int row = fid >> 5;
        int c4  = fid & 31;
        float4 v = make_float4(0.f, 0.f, 0.f, 0.f);
        if (r0 + row < Nn) {
            v = ((const float4*)(in + (size_t)(r0 + row) * Hh))[c4];
            if (apply_f) {
                float4 b = ((const float4*)bprev)[c4];
                v.x = fmaxf(v.x + b.x, 0.f);
                v.y = fmaxf(v.y + b.y, 0.f);
                v.z = fmaxf(v.z + b.z, 0.f);
                v.w = fmaxf(v.w + b.w, 0.f);
            }
        }
        ((float4*)in_s)[fid] = v;
    }
    __syncthreads();

    int tx = tid & 31;   // col group: cols tx*4..tx*4+3
    int ty = tid >> 5;   // row group: rows ty*8..ty*8+7
    float acc[8][4];
#pragma unroll
    for (int r = 0; r < 8; r++)
#pragma unroll
        for (int c = 0; c < 4; c++) acc[r][c] = 0.f;

#pragma unroll 4
    for (int k = 0; k < Hh; k++) {
        float4 b = ((float4*)(W_s + k * Hh))[tx];
        float a[8];
#pragma unroll
        for (int r = 0; r < 8; r++) a[r] = in_s[(ty * 8 + r) * Hh + k];
#pragma unroll
        for (int r = 0; r < 8; r++) {
            acc[r][0] = fmaf(a[r], b.x, acc[r][0]);
            acc[r][1] = fmaf(a[r], b.y, acc[r][1]);
            acc[r][2] = fmaf(a[r], b.z, acc[r][2]);
            acc[r][3] = fmaf(a[r], b.w, acc[r][3]);
        }
    }

#pragma unroll
    for (int r = 0; r < 8; r++) {
        int row = r0 + ty * 8 + r;
        if (row < Nn) {
            float di = g_dinv[row];
            float d2 = di * di;
            float4 hv = make_float4(acc[r][0], acc[r][1], acc[r][2], acc[r][3]);
            ((float4*)(hout + (size_t)row * Hh))[tx] = hv;
            float4 av = make_float4(hv.x * d2, hv.y * d2, hv.z * d2, hv.w * d2);
            ((float4*)(accout + (size_t)row * Hh))[tx] = av;
        }
    }
}

// ------------------------------------------------------------------
// Edge scatter: one warp per edge. acc[d] += h[s] * dinv[s]*dinv[d]
// 128-bit vector RED (sm_90+ float4 atomicAdd)
// ------------------------------------------------------------------
__global__ void scatter_kernel(const int* __restrict__ src, const int* __restrict__ dst,
                               const float* __restrict__ h, float* __restrict__ acc) {
    int warp = (blockIdx.x * blockDim.x + threadIdx.x) >> 5;
    int lane = threadIdx.x & 31;
    if (warp >= Ee) return;
    int s = src[warp];
    int d = dst[warp];
    float w = g_dinv[s] * g_dinv[d];
    float4 v = ((const float4*)(h + (size_t)s * Hh))[lane];
    float4 r = make_float4(v.x * w, v.y * w, v.z * w, v.w * w);
    atomicAdd(((float4*)(acc + (size_t)d * Hh)) + lane, r);
}

// ------------------------------------------------------------------
// Pool: warp per node. pooled[batch[i]] += relu(acc[i] + b3); cnt[g]++
// ------------------------------------------------------------------
__global__ void pool_kernel(const int* __restrict__ batch, const float* __restrict__ acc,
                            const float* __restrict__ b3) {
    int warp = (blockIdx.x * blockDim.x + threadIdx.x) >> 5;
    int lane = threadIdx.x & 31;
    if (warp >= Nn) return;
    int g = batch[warp];
    float4 v = ((const float4*)(acc + (size_t)warp * Hh))[lane];
    float4 b = ((const float4*)b3)[lane];
    v.x = fmaxf(v.x + b.x, 0.f);
    v.y = fmaxf(v.y + b.y, 0.f);
    v.z = fmaxf(v.z + b.z, 0.f);
    v.w = fmaxf(v.w + b.w, 0.f);
    atomicAdd(((float4*)(g_pooled + g * Hh)) + lane, v);
    if (lane == 0) atomicAdd(&g_cnt[g], 1);
}

// ------------------------------------------------------------------
// Final: out[g][c] = (pooled[g]/cnt[g]) . Wl[:,c] + bl[c]   (64x2)
// ------------------------------------------------------------------
__global__ void final_kernel(const float* __restrict__ Wl, const float* __restrict__ bl,
                             float* __restrict__ out) {
    int t = threadIdx.x;        // 128 threads
    int g = t >> 1, c = t & 1;
    float cn = fmaxf((float)g_cnt[g], 1.f);
    float s = 0.f;
#pragma unroll 8
    for (int k = 0; k < Hh; k++)
        s += g_pooled[g * Hh + k] * Wl[k * 2 + c];
    out[g * 2 + c] = s / cn + bl[c];
}

// ------------------------------------------------------------------
extern "C" void kernel_launch(void* const* d_in, const int* in_sizes, int n_in,
                              void* d_out, int out_size) {
    const float* x     = (const float*)d_in[0];
    const int*   ei    = (const int*)d_in[1];   // [2, E] int32
    const int*   batch = (const int*)d_in[2];
    const float* W1 = (const float*)d_in[3];
    const float* b1 = (const float*)d_in[4];
    const float* W2 = (const float*)d_in[5];
    const float* b2 = (const float*)d_in[6];
    const float* W3 = (const float*)d_in[7];
    const float* b3 = (const float*)d_in[8];
    const float* Wl = (const float*)d_in[9];
    const float* bl = (const float*)d_in[10];
    float* out = (float*)d_out;

    const int* src = ei;
    const int* dst = ei + Ee;

    float *hptr, *a0, *a1;
    cudaGetSymbolAddress((void**)&hptr, g_h);
    cudaGetSymbolAddress((void**)&a0, g_acc0);
    cudaGetSymbolAddress((void**)&a1, g_acc1);

    const int SMEM = (64 * Hh + Hh * Hh) * sizeof(float);   // 96 KB
    cudaFuncSetAttribute(gemm_kernel, cudaFuncAttributeMaxDynamicSharedMemorySize, SMEM);

    init_kernel<<<(Nn + 255) / 256, 256>>>();
    deg_kernel<<<(Ee + 255) / 256, 256>>>(dst);
    dinv_kernel<<<(Nn + 255) / 256, 256>>>();

    int gemm_blocks    = (Nn + 63) / 64;
    int scatter_blocks = (Ee + 7) / 8;   // 8 warps (edges) per 256-thread block
    int pool_blocks    = (Nn + 7) / 8;

    // Layer 1: in = x (no transform)
    gemm_kernel<<<gemm_blocks, 256, SMEM>>>(x, W1, nullptr, 0, hptr, a0);
    scatter_kernel<<<scatter_blocks, 256>>>(src, dst, hptr, a0);

    // Layer 2: in = relu(acc0 + b1)
    gemm_kernel<<<gemm_blocks, 256, SMEM>>>(a0, W2, b1, 1, hptr, a1);
    scatter_kernel<<<scatter_blocks, 256>>>(src, dst, hptr, a1);

    // Layer 3: in = relu(acc1 + b2)
    gemm_kernel<<<gemm_blocks, 256, SMEM>>>(a1, W3, b2, 1, hptr, a0);
    scatter_kernel<<<scatter_blocks, 256>>>(src, dst, hptr, a0);

    // Pool: relu(acc0 + b3), segment mean over batch, then tiny linear
    pool_kernel<<<pool_blocks, 256>>>(batch, a0, b3);
    final_kernel<<<1, 128>>>(Wl, bl, out);
}

// round 4
// speedup vs baseline: 1.0266x; 1.0266x over previous
#include <cuda_runtime.h>

#define Nn 50000
#define Ee 600000
#define Hh 128
#define Gg 64

#define SCAN_T 512
#define SCAN_B ((Nn + SCAN_T - 1) / SCAN_T)   // 98

// ---- static scratch ----
__device__ float g_h[Nn * Hh];
__device__ float g_P[Nn * Hh];      // gemm self-loop-init output
__device__ float g_Q[Nn * Hh];      // aggregated output
__device__ float g_dinv[Nn];
__device__ int   g_deg[Nn];
__device__ int   g_aux[Nn];
__device__ int   g_rowptr[Nn + 1];
__device__ int   g_bsum[SCAN_B];
__device__ int   g_boff[SCAN_B];
__device__ int2  g_csr[Ee];
__device__ float g_pooled[Gg * Hh];

// ------------------------------------------------------------------
__global__ void init_kernel() {
    int i = blockIdx.x * blockDim.x + threadIdx.x;
    if (i < Nn) { g_deg[i] = 1; g_aux[i] = 0; }
}

__global__ void deg_kernel(const int* __restrict__ dst) {
    int e = blockIdx.x * blockDim.x + threadIdx.x;
    if (e < Ee) atomicAdd(&g_deg[dst[e]], 1);
}

__global__ void dinv_kernel() {
    int i = blockIdx.x * blockDim.x + threadIdx.x;
    if (i < Nn) g_dinv[i] = rsqrtf((float)g_deg[i]);
}

// ---- scan over cnt = deg-1 to build row_ptr ----
__global__ void scanA_kernel() {
    __shared__ int ws[16];
    int tid = threadIdx.x;
    int i = blockIdx.x * SCAN_T + tid;
    int v = (i < Nn) ? (g_deg[i] - 1) : 0;
#pragma unroll
    for (int o = 16; o; o >>= 1) v += __shfl_down_sync(0xffffffffu, v, o);
    if ((tid & 31) == 0) ws[tid >> 5] = v;
    __syncthreads();
    if (tid < 32) {
        int t = (tid < 16) ? ws[tid] : 0;
#pragma unroll
        for (int o = 8; o; o >>= 1) t += __shfl_down_sync(0xffffffffu, t, o);
        if (tid == 0) g_bsum[blockIdx.x] = t;
    }
}

__global__ void scanB_kernel() {
    // tiny serial exclusive scan of block sums
    int run = 0;
    for (int b = 0; b < SCAN_B; b++) { g_boff[b] = run; run += g_bsum[b]; }
    g_rowptr[Nn] = Ee;
}

__global__ void scanC_kernel() {
    __shared__ int wsum[16], woff[16];
    int tid = threadIdx.x;
    int lane = tid & 31, wid = tid >> 5;
    int i = blockIdx.x * SCAN_T + tid;
    int v = (i < Nn) ? (g_deg[i] - 1) : 0;
    int incl = v;
#pragma unroll
    for (int o = 1; o < 32; o <<= 1) {
        int u = __shfl_up_sync(0xffffffffu, incl, o);
        if (lane >= o) incl += u;
    }
    if (lane == 31) wsum[wid] = incl;
    __syncthreads();
    if (tid < 32) {
        int t = (tid < 16) ? wsum[tid] : 0;
        int inc = t;
#pragma unroll
        for (int o = 1; o < 16; o <<= 1) {
            int u = __shfl_up_sync(0xffffffffu, inc, o);
            if (lane >= o) inc += u;
        }
        if (tid < 16) woff[tid] = inc - t;
    }
    __syncthreads();
    if (i < Nn) g_rowptr[i] = incl - v + woff[wid] + g_boff[blockIdx.x];
}

__global__ void fill_kernel(const int* __restrict__ src, const int* __restrict__ dst) {
    int e = blockIdx.x * blockDim.x + threadIdx.x;
    if (e >= Ee) return;
    int s = src[e], d = dst[e];
    int p = g_rowptr[d] + atomicAdd(&g_aux[d], 1);
    g_csr[p] = make_int2(s, __float_as_int(g_dinv[s] * g_dinv[d]));
}

// ------------------------------------------------------------------
// GEMM: h = f(in) @ W  (f = relu(v+bprev) if apply_f)
// Packed f32x2 FMA. Tile 128x128, 256 threads, 8x8 microtile.
// Epilogue: hout = h, accout = h * dinv^2 (self-loop).
// ------------------------------------------------------------------
__global__ void __launch_bounds__(256, 1)
gemm_kernel(const float* __restrict__ in, const float* __restrict__ W,
            const float* __restrict__ bprev, int apply_f,
            float* __restrict__ hout, float* __restrict__ accout) {
    extern __shared__ float sm[];
    float* in_s = sm;              // [128][128]
    float* W_s  = sm + 128 * 128;  // [128][128]
    int tid = threadIdx.x;
    int r0 = blockIdx.x * 128;

#pragma unroll
    for (int i = 0; i < 16; i++) {
        int fid = tid + i * 256;
        ((float4*)W_s)[fid] = ((const float4*)W)[fid];
    }
#pragma unroll
    for (int i = 0; i < 16; i++) {
        int fid = tid + i * 256;
        int row = fid >> 5, c4 = fid & 31;
        float4 v = make_float4(0.f, 0.f, 0.f, 0.f);
        if (r0 + row < Nn) {
            v = ((const float4*)(in + (size_t)(r0 + row) * Hh))[c4];
            if (apply_f) {
                float4 b = ((const float4*)bprev)[c4];
                v.x = fmaxf(v.x + b.x, 0.f);
                v.y = fmaxf(v.y + b.y, 0.f);
                v.z = fmaxf(v.z + b.z, 0.f);
                v.w = fmaxf(v.w + b.w, 0.f);
            }
        }
        ((float4*)in_s)[fid] = v;
    }
    __syncthreads();

    int tx = tid & 15;   // col octet: cols tx*8 .. tx*8+7
    int ty = tid >> 4;   // row octet: rows ty*8 .. ty*8+7

    unsigned long long acc[8][4];
#pragma unroll
    for (int r = 0; r < 8; r++)
#pragma unroll
        for (int c = 0; c < 4; c++) acc[r][c] = 0ull;

#pragma unroll 8
    for (int k = 0; k < Hh; k++) {
        const longlong2* bp = (const longlong2*)(W_s + k * Hh + tx * 8);
        longlong2 p0 = bp[0], p1 = bp[1];
        unsigned long long b2[4] = {(unsigned long long)p0.x, (unsigned long long)p0.y,
                                    (unsigned long long)p1.x, (unsigned long long)p1.y};
#pragma unroll
        for (int r = 0; r < 8; r++) {
            float a = in_s[(ty * 8 + r) * Hh + k];
            unsigned long long a2;
            asm("mov.b64 %0, {%1, %1};" : "=l"(a2) : "f"(a));
#pragma unroll
            for (int c = 0; c < 4; c++)
                asm("fma.rn.f32x2 %0, %1, %2, %0;" : "+l"(acc[r][c]) : "l"(a2), "l"(b2[c]));
        }
    }

#pragma unroll
    for (int r = 0; r < 8; r++) {
        int row = r0 + ty * 8 + r;
        if (row < Nn) {
            float di = g_dinv[row];
            float d2 = di * di;
            float v[8];
#pragma unroll
            for (int c = 0; c < 4; c++)
                asm("mov.b64 {%0, %1}, %2;" : "=f"(v[2 * c]), "=f"(v[2 * c + 1]) : "l"(acc[r][c]));
            float4* hp = (float4*)(hout + (size_t)row * Hh + tx * 8);
            float4* ap = (float4*)(accout + (size_t)row * Hh + tx * 8);
            hp[0] = make_float4(v[0], v[1], v[2], v[3]);
            hp[1] = make_float4(v[4], v[5], v[6], v[7]);
            ap[0] = make_float4(v[0] * d2, v[1] * d2, v[2] * d2, v[3] * d2);
            ap[1] = make_float4(v[4] * d2, v[5] * d2, v[6] * d2, v[7] * d2);
        }
    }
}

// ------------------------------------------------------------------
// Aggregation: warp per node, non-atomic.
// out[i] = init[i] + sum_{edges j->i} w_j * h[src_j]
// ------------------------------------------------------------------
__global__ void agg_kernel(const float* __restrict__ h, const float* __restrict__ init,
                           float* __restrict__ out) {
    int warp = (blockIdx.x * blockDim.x + threadIdx.x) >> 5;
    int lane = threadIdx.x & 31;
    if (warp >= Nn) return;
    int beg = g_rowptr[warp], end = g_rowptr[warp + 1];
    float4 acc = ((const float4*)(init + (size_t)warp * Hh))[lane];
    int2 e = make_int2(0, 0);
    if (beg < end) e = g_csr[beg];
    for (int j = beg; j < end; j++) {
        int2 cur = e;
        if (j + 1 < end) e = g_csr[j + 1];
        float w = __int_as_float(cur.y);
        float4 v = ((const float4*)(h + (size_t)cur.x * Hh))[lane];
        acc.x = fmaf(w, v.x, acc.x);
        acc.y = fmaf(w, v.y, acc.y);
        acc.z = fmaf(w, v.z, acc.z);
        acc.w = fmaf(w, v.w, acc.w);
    }
    ((float4*)(out + (size_t)warp * Hh))[lane] = acc;
}

// ------------------------------------------------------------------
// Pool: one block per graph (batch is sorted). No atomics.
// ------------------------------------------------------------------
__device__ __forceinline__ int lower_bound_dev(const int* a, int n, int key) {
    int lo = 0, hi = n;
    while (lo < hi) {
        int mid = (lo + hi) >> 1;
        if (a[mid] < key) lo = mid + 1; else hi = mid;
    }
    return lo;
}

__global__ void pool_kernel(const int* __restrict__ batch, const float* __restrict__ acc,
                            const float* __restrict__ b3) {
    int g = blockIdx.x;
    int f = threadIdx.x;   // 128 feats
    __shared__ int s_lo, s_hi;
    if (f == 0) s_lo = lower_bound_dev(batch, Nn, g);
    if (f == 1) s_hi = lower_bound_dev(batch, Nn, g + 1);
    __syncthreads();
    int lo = s_lo, hi = s_hi;
    float b = b3[f];
    float s0 = 0.f, s1 = 0.f, s2 = 0.f, s3 = 0.f;
    int n = lo;
    for (; n + 4 <= hi; n += 4) {
        s0 += fmaxf(acc[(size_t)(n + 0) * Hh + f] + b, 0.f);
        s1 += fmaxf(acc[(size_t)(n + 1) * Hh + f] + b, 0.f);
        s2 += fmaxf(acc[(size_t)(n + 2) * Hh + f] + b, 0.f);
        s3 += fmaxf(acc[(size_t)(n + 3) * Hh + f] + b, 0.f);
    }
    for (; n < hi; n++) s0 += fmaxf(acc[(size_t)n * Hh + f] + b, 0.f);
    float s = (s0 + s1) + (s2 + s3);
    g_pooled[g * Hh + f] = s / fmaxf((float)(hi - lo), 1.f);
}

__global__ void final_kernel(const float* __restrict__ Wl, const float* __restrict__ bl,
                             float* __restrict__ out) {
    int t = threadIdx.x;  // 128
    int g = t >> 1, c = t & 1;
    float s = 0.f;
#pragma unroll 8
    for (int k = 0; k < Hh; k++)
        s += g_pooled[g * Hh + k] * Wl[k * 2 + c];
    out[g * 2 + c] = s + bl[c];
}

// ------------------------------------------------------------------
extern "C" void kernel_launch(void* const* d_in, const int* in_sizes, int n_in,
                              void* d_out, int out_size) {
    const float* x     = (const float*)d_in[0];
    const int*   ei    = (const int*)d_in[1];
    const int*   batch = (const int*)d_in[2];
    const float* W1 = (const float*)d_in[3];
    const float* b1 = (const float*)d_in[4];
    const float* W2 = (const float*)d_in[5];
    const float* b2 = (const float*)d_in[6];
    const float* W3 = (const float*)d_in[7];
    const float* b3 = (const float*)d_in[8];
    const float* Wl = (const float*)d_in[9];
    const float* bl = (const float*)d_in[10];
    float* out = (float*)d_out;

    const int* src = ei;
    const int* dst = ei + Ee;

    float *hptr, *P, *Q;
    cudaGetSymbolAddress((void**)&hptr, g_h);
    cudaGetSymbolAddress((void**)&P, g_P);
    cudaGetSymbolAddress((void**)&Q, g_Q);

    const int SMEM = 2 * Hh * Hh * sizeof(float);   // 128 KB
    cudaFuncSetAttribute(gemm_kernel, cudaFuncAttributeMaxDynamicSharedMemorySize, SMEM);

    // preprocessing (per replay, deterministic work)
    init_kernel<<<(Nn + 255) / 256, 256>>>();
    deg_kernel<<<(Ee + 255) / 256, 256>>>(dst);
    dinv_kernel<<<(Nn + 255) / 256, 256>>>();
    scanA_kernel<<<SCAN_B, SCAN_T>>>();
    scanB_kernel<<<1, 1>>>();
    scanC_kernel<<<SCAN_B, SCAN_T>>>();
    fill_kernel<<<(Ee + 255) / 256, 256>>>(src, dst);

    int gemm_blocks = (Nn + 127) / 128;              // 391
    int agg_blocks  = (Nn * 32 + 255) / 256;         // warp per node

    // Layer 1
    gemm_kernel<<<gemm_blocks, 256, SMEM>>>(x, W1, nullptr, 0, hptr, P);
    agg_kernel<<<agg_blocks, 256>>>(hptr, P, Q);
    // Layer 2
    gemm_kernel<<<gemm_blocks, 256, SMEM>>>(Q, W2, b1, 1, hptr, P);
    agg_kernel<<<agg_blocks, 256>>>(hptr, P, Q);
    // Layer 3
    gemm_kernel<<<gemm_blocks, 256, SMEM>>>(Q, W3, b2, 1, hptr, P);
    agg_kernel<<<agg_blocks, 256>>>(hptr, P, Q);

    // Pool + head
    pool_kernel<<<Gg, Hh>>>(batch, Q, b3);
    final_kernel<<<1, 128>>>(Wl, bl, out);
}